// round 5
// baseline (speedup 1.0000x reference)
#include <cuda_runtime.h>
#include <cstdint>
#include <cstddef>

#define BB 8
#define NN 2048
#define DD 128

// ---------------- scratch (no allocs allowed) ----------------
__device__ float g_zn[BB * NN * DD];    // Z  [b][token][feat], tf32-rounded bits
__device__ float g_x [BB * NN * DD];    // layer activations [b][token][feat]
__device__ float g_invden[BB * NN];

typedef unsigned long long u64;

// ---------------- small PTX helpers ----------------
__device__ __forceinline__ uint32_t smem_u32(const void* p) {
    uint32_t a;
    asm("{ .reg .u64 t; cvta.to.shared.u64 t, %1; cvt.u32.u64 %0, t; }" : "=r"(a) : "l"(p));
    return a;
}
__device__ __forceinline__ void cp16(uint32_t dst, const void* src) {
    asm volatile("cp.async.cg.shared.global [%0], [%1], 16;" :: "r"(dst), "l"(src));
}
__device__ __forceinline__ void cp_commit() {
    asm volatile("cp.async.commit_group;" ::: "memory");
}
__device__ __forceinline__ uint32_t cvt_tf32(float x) {
    uint32_t r; asm("cvt.rna.tf32.f32 %0, %1;" : "=r"(r) : "f"(x)); return r;
}
// m16n8k8 tf32 HMMA, fp32 accumulate (plain sm_80+ path — works on target 'sm_103')
__device__ __forceinline__ void mma_tf32(float* d,
    uint32_t a0, uint32_t a1, uint32_t a2, uint32_t a3,
    uint32_t b0, uint32_t b1)
{
    asm volatile(
        "mma.sync.aligned.m16n8k8.row.col.f32.tf32.tf32.f32 "
        "{%0,%1,%2,%3}, {%4,%5,%6,%7}, {%8,%9}, {%0,%1,%2,%3};"
        : "+f"(d[0]), "+f"(d[1]), "+f"(d[2]), "+f"(d[3])
        : "r"(a0), "r"(a1), "r"(a2), "r"(a3), "r"(b0), "r"(b1));
}

// f32x2 helpers (zk kernel)
__device__ __forceinline__ void fma2(u64 &c, u64 a, u64 b) {
    asm("fma.rn.f32x2 %0, %1, %2, %0;" : "+l"(c) : "l"(a), "l"(b));
}
__device__ __forceinline__ float2 unpack2(u64 v) {
    float2 r; asm("mov.b64 {%0, %1}, %2;" : "=f"(r.x), "=f"(r.y) : "l"(v)); return r;
}

// =================================================================
//  AX kernel (tf32 HMMA): out = relu((A @ Z + bias) * invden)
//  A fp32 streamed raw (cvt.rna on fragments). Z token-major [t][f],
//  tf32-pre-rounded; B frags read as Zs[k][n] (transpose-by-indexing).
//  CTA 64(M) x 128(N), 4 warps (warp tile 32x64), BK=32, 3-stage cp.async.
// =================================================================
#define APAD 36                       // A smem floats/row (144 B)
#define ZPAD 136                      // Z smem floats/row (544 B)
#define A_TILE_B (64 * APAD * 4)      // 9216
#define Z_TILE_B (32 * ZPAD * 4)      // 17408
#define STAGE_B (A_TILE_B + Z_TILE_B) // 26624
#define AX_SMEM (1024 + 3 * STAGE_B)  // 80896

template<bool FIRST>
__global__ __launch_bounds__(128, 2) void ax_hmma(
    const float* __restrict__ A,
    const float* __restrict__ Zn,
    const float* __restrict__ bias,
    const float* __restrict__ invden_g,
    float* __restrict__ invden_out,
    float* __restrict__ Out)
{
    extern __shared__ __align__(16) char sm[];
    float* sb   = reinterpret_cast<float*>(sm);       // bias [128]
    float* sinv = sb + 128;                           // invden [64]
    const uint32_t smb = smem_u32(sm);

    const int tid = threadIdx.x, lane = tid & 31, wid = tid >> 5;
    const int b = blockIdx.y, m0 = blockIdx.x * 64;

    sb[tid] = bias[tid];
    if (!FIRST && tid < 64) sinv[tid] = invden_g[(size_t)b * NN + m0 + tid];
    __syncthreads();

    // loaders: A tile 64x32 (16 floats/thr), Z tile 32 tokens x 128 feats (32 floats/thr)
    const int arow = tid >> 1, ahalf = tid & 1;
    const int ztok = tid >> 2, zq = tid & 3;
    const float* agl = A  + ((size_t)b * NN + m0 + arow) * NN + ahalf * 16;
    const float* zgl = Zn + ((size_t)b * NN + ztok) * DD + zq * 32;
    const uint32_t adst = (uint32_t)(arow * (APAD * 4) + ahalf * 64);
    const uint32_t zdst = (uint32_t)(A_TILE_B + ztok * (ZPAD * 4) + zq * 128);

    auto load_chunk = [&](int i) {
        const int s = i % 3;
        const uint32_t base = smb + 1024 + s * STAGE_B;
        const float* sa = agl + i * 32;
        const float* sz = zgl + (size_t)i * 32 * DD;
        const uint32_t da = base + adst;
        cp16(da,      sa);      cp16(da + 16, sa + 4);
        cp16(da + 32, sa + 8);  cp16(da + 48, sa + 12);
        const uint32_t dz = base + zdst;
        #pragma unroll
        for (int q = 0; q < 8; q++) cp16(dz + q * 16, sz + q * 4);
        cp_commit();
    };

    // compute mapping: warp grid 2(M) x 2(N), warp tile 32x64
    const int g = lane >> 2, c = lane & 3;
    const int wm = (wid & 1) * 32, wn = (wid >> 1) * 64;

    float acc[2][8][4];
    #pragma unroll
    for (int mi = 0; mi < 2; mi++)
        #pragma unroll
        for (int nj = 0; nj < 8; nj++)
            #pragma unroll
            for (int q = 0; q < 4; q++) acc[mi][nj][q] = 0.f;

    float rs = 0.f;

    load_chunk(0);
    load_chunk(1);

    #pragma unroll 1
    for (int i = 0; i < 64; i++) {
        if (i < 62) { asm volatile("cp.async.wait_group 1;" ::: "memory"); }
        else        { asm volatile("cp.async.wait_group 0;" ::: "memory"); }
        __syncthreads();
        if (i < 62) load_chunk(i + 2);

        const float* As = reinterpret_cast<const float*>(sm + 1024 + (i % 3) * STAGE_B);
        const uint32_t* Zu = reinterpret_cast<const uint32_t*>(As + 64 * APAD);

        if (FIRST) {  // layer-0 rowsum of A chunk (from smem)
            const float4* ar = reinterpret_cast<const float4*>(As + arow * APAD + ahalf * 16);
            float4 v0 = ar[0], v1 = ar[1], v2 = ar[2], v3 = ar[3];
            rs += (v0.x + v0.y + v0.z + v0.w) + (v1.x + v1.y + v1.z + v1.w)
                + (v2.x + v2.y + v2.z + v2.w) + (v3.x + v3.y + v3.z + v3.w);
        }

        #pragma unroll
        for (int ks = 0; ks < 4; ks++) {
            const int kk = ks * 8 + c;
            uint32_t a0[4], a1[4];
            a0[0] = cvt_tf32(As[(wm + g)      * APAD + kk]);
            a0[1] = cvt_tf32(As[(wm + g + 8)  * APAD + kk]);
            a0[2] = cvt_tf32(As[(wm + g)      * APAD + kk + 4]);
            a0[3] = cvt_tf32(As[(wm + g + 8)  * APAD + kk + 4]);
            a1[0] = cvt_tf32(As[(wm + 16 + g)     * APAD + kk]);
            a1[1] = cvt_tf32(As[(wm + 24 + g)     * APAD + kk]);
            a1[2] = cvt_tf32(As[(wm + 16 + g)     * APAD + kk + 4]);
            a1[3] = cvt_tf32(As[(wm + 24 + g)     * APAD + kk + 4]);
            #pragma unroll
            for (int nj = 0; nj < 8; nj++) {
                const int col = wn + 8 * nj + g;
                uint32_t b0 = Zu[kk       * ZPAD + col];
                uint32_t b1 = Zu[(kk + 4) * ZPAD + col];
                mma_tf32(acc[0][nj], a0[0], a0[1], a0[2], a0[3], b0, b1);
                mma_tf32(acc[1][nj], a1[0], a1[1], a1[2], a1[3], b0, b1);
            }
        }
    }

    if (FIRST) {
        float stot = rs + __shfl_xor_sync(0xffffffffu, rs, 1);  // tid^1 shares arow
        float inv = 1.0f / (stot + 1.0f);
        if (ahalf == 0) {
            sinv[arow] = inv;
            invden_out[(size_t)b * NN + m0 + arow] = inv;
        }
        __syncthreads();
    }

    // ---- epilogue: bias + *invden + relu ----
    #pragma unroll
    for (int mi = 0; mi < 2; mi++) {
        const int r_lo = wm + 16 * mi + g;
        const int r_hi = r_lo + 8;
        const float inv_lo = sinv[r_lo];
        const float inv_hi = sinv[r_hi];
        float* o_lo = Out + ((size_t)b * NN + m0 + r_lo) * DD;
        float* o_hi = Out + ((size_t)b * NN + m0 + r_hi) * DD;
        #pragma unroll
        for (int nj = 0; nj < 8; nj++) {
            const int col = wn + 8 * nj + 2 * c;
            const float b0f = sb[col], b1f = sb[col + 1];
            float2 vlo, vhi;
            vlo.x = fmaxf((acc[mi][nj][0] + b0f) * inv_lo, 0.f);
            vlo.y = fmaxf((acc[mi][nj][1] + b1f) * inv_lo, 0.f);
            vhi.x = fmaxf((acc[mi][nj][2] + b0f) * inv_hi, 0.f);
            vhi.y = fmaxf((acc[mi][nj][3] + b1f) * inv_hi, 0.f);
            *reinterpret_cast<float2*>(o_lo + col) = vlo;
            *reinterpret_cast<float2*>(o_hi + col) = vhi;
        }
    }
}

// =================================================================
//  zk kernel (f32x2 SIMT): Z = X @ W, plain [token][feat] output,
//  tf32-rounded, coalesced float4 stores. Tile 64 x 128, 256 CTAs.
// =================================================================
__global__ __launch_bounds__(256, 1) void zk64(
    const float* __restrict__ X, const float* __restrict__ W,
    float* __restrict__ Zn)
{
    __shared__ __align__(16) float As[2][8][68];    // [buf][k][token] transposed
    __shared__ __align__(16) float Bd[2][8][256];   // [buf][k][dup planes]

    const int tid = threadIdx.x;
    const int m0g = blockIdx.x * 64;                // global token index

    const int tx = tid & 15, ty = tid >> 4;
    const int r = ty * 4, c0 = tx * 4;

    const int arow = tid >> 1, ahalf = tid & 1;     // A loader (tid<128)
    const int bk = tid >> 5, bn = (tid & 31) * 4;   // B loader (all)

    u64 acc[2][8];
    #pragma unroll
    for (int i = 0; i < 2; i++)
        #pragma unroll
        for (int j = 0; j < 8; j++) acc[i][j] = 0ull;

    float4 va, vb;
    auto ldg = [&](int k0) {
        if (tid < 128)
            va = *reinterpret_cast<const float4*>(
                X + (size_t)(m0g + arow) * DD + k0 + ahalf * 4);
        vb = *reinterpret_cast<const float4*>(
                W + (size_t)(k0 + bk) * DD + bn);
    };
    auto sts = [&](int s) {
        if (tid < 128) {
            As[s][ahalf * 4 + 0][arow] = va.x;
            As[s][ahalf * 4 + 1][arow] = va.y;
            As[s][ahalf * 4 + 2][arow] = va.z;
            As[s][ahalf * 4 + 3][arow] = va.w;
        }
        *reinterpret_cast<float4*>(&Bd[s][bk][bn])       = make_float4(vb.x, vb.x, vb.y, vb.y);
        *reinterpret_cast<float4*>(&Bd[s][bk][128 + bn]) = make_float4(vb.z, vb.z, vb.w, vb.w);
    };
    auto comp = [&](int s) {
        #pragma unroll
        for (int k = 0; k < 8; k++) {
            ulonglong2 aA = *reinterpret_cast<const ulonglong2*>(&As[s][k][r]);
            ulonglong2 p0 = *reinterpret_cast<const ulonglong2*>(&Bd[s][k][4 * tx]);
            ulonglong2 p1 = *reinterpret_cast<const ulonglong2*>(&Bd[s][k][128 + 4 * tx]);
            ulonglong2 p2 = *reinterpret_cast<const ulonglong2*>(&Bd[s][k][64 + 4 * tx]);
            ulonglong2 p3 = *reinterpret_cast<const ulonglong2*>(&Bd[s][k][192 + 4 * tx]);
            u64 bq[8] = {p0.x, p0.y, p1.x, p1.y, p2.x, p2.y, p3.x, p3.y};
            #pragma unroll
            for (int j = 0; j < 8; j++) {
                fma2(acc[0][j], aA.x, bq[j]);
                fma2(acc[1][j], aA.y, bq[j]);
            }
        }
    };

    ldg(0); sts(0);
    __syncthreads();
    #pragma unroll 1
    for (int t = 0; t < 16; t++) {
        if (t < 15) ldg((t + 1) * 8);
        comp(t & 1);
        if (t < 15) sts((t + 1) & 1);
        __syncthreads();
    }

    // epilogue: plain [token][feat] coalesced uint4 stores (tf32-rounded)
    float2 ua[8], ub[8];
    #pragma unroll
    for (int j = 0; j < 8; j++) { ua[j] = unpack2(acc[0][j]); ub[j] = unpack2(acc[1][j]); }

    auto st = [&](int row, int colbase, float v0, float v1, float v2, float v3) {
        uint4 o;
        o.x = cvt_tf32(v0); o.y = cvt_tf32(v1); o.z = cvt_tf32(v2); o.w = cvt_tf32(v3);
        *reinterpret_cast<uint4*>(Zn + (size_t)(m0g + row) * DD + colbase) = o;
    };
    st(r + 0, c0,      ua[0].x, ua[1].x, ua[2].x, ua[3].x);
    st(r + 0, c0 + 64, ua[4].x, ua[5].x, ua[6].x, ua[7].x);
    st(r + 1, c0,      ua[0].y, ua[1].y, ua[2].y, ua[3].y);
    st(r + 1, c0 + 64, ua[4].y, ua[5].y, ua[6].y, ua[7].y);
    st(r + 2, c0,      ub[0].x, ub[1].x, ub[2].x, ub[3].x);
    st(r + 2, c0 + 64, ub[4].x, ub[5].x, ub[6].x, ub[7].x);
    st(r + 3, c0,      ub[0].y, ub[1].y, ub[2].y, ub[3].y);
    st(r + 3, c0 + 64, ub[4].y, ub[5].y, ub[6].y, ub[7].y);
}

// =================================================================
extern "C" void kernel_launch(void* const* d_in, const int* in_sizes, int n_in,
                              void* d_out, int out_size)
{
    const float *inputs = nullptr, *adj = nullptr, *W = nullptr, *bias = nullptr;
    for (int i = 0; i < n_in; i++) {
        const long long s = in_sizes[i];
        if      (s == (long long)BB * NN * DD) inputs = (const float*)d_in[i];
        else if (s == (long long)BB * NN * NN) adj    = (const float*)d_in[i];
        else if (s == 3LL * DD * DD)           W      = (const float*)d_in[i];
        else if (s == 3LL * DD)                bias   = (const float*)d_in[i];
    }
    float* out = (float*)d_out;

    float *zn, *x, *invd;
    cudaGetSymbolAddress((void**)&zn,   g_zn);
    cudaGetSymbolAddress((void**)&x,    g_x);
    cudaGetSymbolAddress((void**)&invd, g_invden);

    static bool attr_done = false;
    if (!attr_done) {
        cudaFuncSetAttribute(ax_hmma<true>,  cudaFuncAttributeMaxDynamicSharedMemorySize, AX_SMEM);
        cudaFuncSetAttribute(ax_hmma<false>, cudaFuncAttributeMaxDynamicSharedMemorySize, AX_SMEM);
        attr_done = true;
    }

    const dim3 gAX(NN / 64, BB);              // 32 x 8 = 256 CTAs
    const dim3 gZK((BB * NN) / 64, 1);        // 256 CTAs

    // layer 0
    zk64<<<gZK, 256>>>(inputs, W, zn);
    ax_hmma<true><<<gAX, 128, AX_SMEM>>>(adj, zn, bias, nullptr, invd, x);
    // layer 1
    zk64<<<gZK, 256>>>(x, W + DD * DD, zn);
    ax_hmma<false><<<gAX, 128, AX_SMEM>>>(adj, zn, bias + DD, invd, nullptr, x);
    // layer 2
    zk64<<<gZK, 256>>>(x, W + 2 * DD * DD, zn);
    ax_hmma<false><<<gAX, 128, AX_SMEM>>>(adj, zn, bias + 2 * DD, invd, nullptr, out);
}

// round 6
// speedup vs baseline: 1.4768x; 1.4768x over previous
#include <cuda_runtime.h>
#include <cstdint>
#include <cstddef>

#define BB 8
#define NN 2048
#define DD 128

// ---------------- scratch (no allocs allowed) ----------------
__device__ float g_zp  [BB * NN * DD];        // Z pair-packed [b][k2][n][2], tf32 bits
__device__ float g_x   [BB * NN * DD];        // activations [b][token][feat]
__device__ float g_part[2 * BB * NN * DD];    // split-K partials
__device__ float g_rs  [2 * BB * NN];         // split-K partial rowsums (layer 0)
__device__ float g_invden[BB * NN];

typedef unsigned long long u64;

// ---------------- PTX helpers ----------------
__device__ __forceinline__ uint32_t smem_u32(const void* p) {
    uint32_t a;
    asm("{ .reg .u64 t; cvta.to.shared.u64 t, %1; cvt.u32.u64 %0, t; }" : "=r"(a) : "l"(p));
    return a;
}
__device__ __forceinline__ void cp16(uint32_t dst, const void* src) {
    asm volatile("cp.async.cg.shared.global [%0], [%1], 16;" :: "r"(dst), "l"(src));
}
__device__ __forceinline__ void cp_commit() {
    asm volatile("cp.async.commit_group;" ::: "memory");
}
__device__ __forceinline__ uint32_t cvt_tf32(float x) {
    uint32_t r; asm("cvt.rna.tf32.f32 %0, %1;" : "=r"(r) : "f"(x)); return r;
}
// m16n8k8 tf32 HMMA, fp32 accumulate (plain sm_80+ encoding, valid on target sm_103)
__device__ __forceinline__ void mma_tf32(float* d,
    uint32_t a0, uint32_t a1, uint32_t a2, uint32_t a3,
    uint32_t b0, uint32_t b1)
{
    asm volatile(
        "mma.sync.aligned.m16n8k8.row.col.f32.tf32.tf32.f32 "
        "{%0,%1,%2,%3}, {%4,%5,%6,%7}, {%8,%9}, {%0,%1,%2,%3};"
        : "+f"(d[0]), "+f"(d[1]), "+f"(d[2]), "+f"(d[3])
        : "r"(a0), "r"(a1), "r"(a2), "r"(a3), "r"(b0), "r"(b1));
}

// ---------------- smem geometry ----------------
#define APAD  36                          // A floats/row (144 B)
#define ZPW   264                         // pair-packed Z: words per k2 row (1056 B)
#define WPAD  136                         // W floats/row (544 B)
#define A_TILE_B (128 * APAD * 4)         // 18432
#define B_TILE_B (32 * WPAD * 4)          // 17408 (>= 16*ZPW*4 = 16896)
#define STB (A_TILE_B + B_TILE_B)         // 35840
#define SMEM_T (1024 + 3 * STB)           // 108544

// =================================================================
//  Unified tf32-HMMA GEMM, CTA tile 128(M) x 128(N), 8 warps
//  (warp tile 32x64), BK=32, 3-stage cp.async, occupancy 2.
//  Modes:
//   AX  (BPAIR=1, ZSTORE=0): A=adj (fp32 raw, cvt at frag), B=Zp
//        pair-packed tf32; split-K via blockIdx.z; writes raw
//        partials to g_part (+partial rowsums when FIRST).
//   ZK  (BPAIR=0, ZSTORE=1): A=X, B=W (both cvt at frag);
//        epilogue writes pair-packed tf32 Z to g_zp.
// =================================================================
template<int NCH, bool BPAIR, bool FIRST, bool ZSTORE>
__global__ __launch_bounds__(256, 2) void gk(
    const float* __restrict__ Aop, int lda,
    const float* __restrict__ Bop,
    float* __restrict__ Pout,
    float* __restrict__ rsOut)
{
    extern __shared__ __align__(16) char sm[];
    const uint32_t smb = smem_u32(sm);

    const int tid = threadIdx.x, lane = tid & 31, wid = tid >> 5;
    const int b  = BPAIR ? blockIdx.y : 0;
    const int z  = BPAIR ? blockIdx.z : 0;
    const int m0 = blockIdx.x * 128;
    const int rowBase = BPAIR ? (b * NN + m0) : m0;
    const int kOff = z * (NCH * 32);

    // ---- loaders ----
    const int arow = tid >> 1, ahalf = tid & 1;
    const float* aGlob = Aop + (size_t)(rowBase + arow) * lda + kOff + ahalf * 16;
    const uint32_t adst = (uint32_t)(arow * (APAD * 4) + ahalf * 64);

    // BPAIR src: contiguous 4096-float blocks per chunk; thread takes 16 floats
    const float* bGlobP = BPAIR ? (Bop + (size_t)b * NN * DD + (size_t)(kOff / 32) * 4096 + tid * 16)
                                : nullptr;
    const uint32_t bdstP = (uint32_t)(A_TILE_B + (tid >> 4) * (ZPW * 4) + (tid & 15) * 64);
    // W src: rows [k][n]
    const int wkr = tid >> 3, wkc = (tid & 7) * 16;
    const float* bGlobW = BPAIR ? nullptr : (Bop + (size_t)wkr * DD + wkc);
    const uint32_t bdstW = (uint32_t)(A_TILE_B + wkr * (WPAD * 4) + wkc * 4);

    auto load_chunk = [&](int i) {
        const uint32_t base = smb + 1024 + (i % 3) * STB;
        const float* sa = aGlob + i * 32;
        const uint32_t da = base + adst;
        cp16(da,      sa);      cp16(da + 16, sa + 4);
        cp16(da + 32, sa + 8);  cp16(da + 48, sa + 12);
        if (BPAIR) {
            const float* sz = bGlobP + (size_t)i * 4096;
            const uint32_t dz = base + bdstP;
            cp16(dz,      sz);      cp16(dz + 16, sz + 4);
            cp16(dz + 32, sz + 8);  cp16(dz + 48, sz + 12);
        } else {
            const float* sw = bGlobW + (size_t)i * 32 * DD;
            const uint32_t dw = base + bdstW;
            cp16(dw,      sw);      cp16(dw + 16, sw + 4);
            cp16(dw + 32, sw + 8);  cp16(dw + 48, sw + 12);
        }
        cp_commit();
    };

    // ---- compute mapping: warp grid 4(M) x 2(N) ----
    const int g = lane >> 2, c = lane & 3;
    const int wm = (wid & 3) * 32, wn = (wid >> 2) * 64;

    float acc[2][8][4];
    #pragma unroll
    for (int mi = 0; mi < 2; mi++)
        #pragma unroll
        for (int nj = 0; nj < 8; nj++)
            #pragma unroll
            for (int q = 0; q < 4; q++) acc[mi][nj][q] = 0.f;

    float rs = 0.f;

    load_chunk(0);
    load_chunk(1);

    #pragma unroll 1
    for (int i = 0; i < NCH; i++) {
        if (i < NCH - 2) { asm volatile("cp.async.wait_group 1;" ::: "memory"); }
        else             { asm volatile("cp.async.wait_group 0;" ::: "memory"); }
        __syncthreads();
        if (i < NCH - 2) load_chunk(i + 2);

        const float* As = reinterpret_cast<const float*>(sm + 1024 + (i % 3) * STB);
        const uint32_t* Bu = reinterpret_cast<const uint32_t*>(As + A_TILE_B / 4);

        if (FIRST) {   // partial rowsum of A chunk (from smem)
            const float4* ar = reinterpret_cast<const float4*>(As + arow * APAD + ahalf * 16);
            float4 v0 = ar[0], v1 = ar[1], v2 = ar[2], v3 = ar[3];
            rs += (v0.x + v0.y + v0.z + v0.w) + (v1.x + v1.y + v1.z + v1.w)
                + (v2.x + v2.y + v2.z + v2.w) + (v3.x + v3.y + v3.z + v3.w);
        }

        #pragma unroll
        for (int ks = 0; ks < 4; ks++) {
            const int kk = ks * 8 + c;
            uint32_t a0[4], a1[4];
            a0[0] = cvt_tf32(As[(wm + g)      * APAD + kk]);
            a0[1] = cvt_tf32(As[(wm + g + 8)  * APAD + kk]);
            a0[2] = cvt_tf32(As[(wm + g)      * APAD + kk + 4]);
            a0[3] = cvt_tf32(As[(wm + g + 8)  * APAD + kk + 4]);
            a1[0] = cvt_tf32(As[(wm + 16 + g) * APAD + kk]);
            a1[1] = cvt_tf32(As[(wm + 24 + g) * APAD + kk]);
            a1[2] = cvt_tf32(As[(wm + 16 + g) * APAD + kk + 4]);
            a1[3] = cvt_tf32(As[(wm + 24 + g) * APAD + kk + 4]);
            #pragma unroll
            for (int nj = 0; nj < 8; nj++) {
                const int col = wn + 8 * nj + g;
                uint32_t b0, b1;
                if (BPAIR) {
                    uint2 bb = *reinterpret_cast<const uint2*>(
                        Bu + (ks * 4 + c) * ZPW + col * 2);
                    b0 = bb.x; b1 = bb.y;
                } else {
                    b0 = cvt_tf32(__uint_as_float(Bu[(ks * 8 + c)     * WPAD + col]));
                    b1 = cvt_tf32(__uint_as_float(Bu[(ks * 8 + c + 4) * WPAD + col]));
                }
                mma_tf32(acc[0][nj], a0[0], a0[1], a0[2], a0[3], b0, b1);
                mma_tf32(acc[1][nj], a1[0], a1[1], a1[2], a1[3], b0, b1);
            }
        }
    }

    if (FIRST) {
        float stot = rs + __shfl_xor_sync(0xffffffffu, rs, 1);   // tid^1 shares arow
        if (ahalf == 0)
            rsOut[(size_t)(z * BB + b) * NN + m0 + arow] = stot;
    }

    // ---- epilogue ----
    if (ZSTORE) {
        // write pair-packed tf32 Z: [b][k2][n][2]
        const int zb   = (blockIdx.x * 128) >> 11;
        const int tLoc = (blockIdx.x * 128) & 2047;
        float* zout = Pout + (size_t)zb * NN * DD;
        #pragma unroll
        for (int mi = 0; mi < 2; mi++) {
            const int r_lo = wm + 16 * mi + g;
            const int t_lo = tLoc + r_lo, t_hi = t_lo + 8;
            const int k2l = (t_lo >> 3) * 4 + (t_lo & 3), sl = (t_lo >> 2) & 1;
            const int k2h = (t_hi >> 3) * 4 + (t_hi & 3), sh = (t_hi >> 2) & 1;
            #pragma unroll
            for (int nj = 0; nj < 8; nj++) {
                const int col = wn + 8 * nj + 2 * c;
                zout[(k2l * 128 + col)     * 2 + sl] = __uint_as_float(cvt_tf32(acc[mi][nj][0]));
                zout[(k2l * 128 + col + 1) * 2 + sl] = __uint_as_float(cvt_tf32(acc[mi][nj][1]));
                zout[(k2h * 128 + col)     * 2 + sh] = __uint_as_float(cvt_tf32(acc[mi][nj][2]));
                zout[(k2h * 128 + col + 1) * 2 + sh] = __uint_as_float(cvt_tf32(acc[mi][nj][3]));
            }
        }
    } else {
        // raw split-K partials
        float* pb = Pout + (size_t)(z * BB + b) * NN * DD;
        #pragma unroll
        for (int mi = 0; mi < 2; mi++) {
            const int r_lo = wm + 16 * mi + g;
            float* o_lo = pb + (size_t)(m0 + r_lo) * DD;
            float* o_hi = pb + (size_t)(m0 + r_lo + 8) * DD;
            #pragma unroll
            for (int nj = 0; nj < 8; nj++) {
                const int col = wn + 8 * nj + 2 * c;
                *reinterpret_cast<float2*>(o_lo + col) =
                    make_float2(acc[mi][nj][0], acc[mi][nj][1]);
                *reinterpret_cast<float2*>(o_hi + col) =
                    make_float2(acc[mi][nj][2], acc[mi][nj][3]);
            }
        }
    }
}

// =================================================================
//  Reduce kernel: out = relu((p0 + p1 + bias) * invden)
//  FIRST: invden computed from partial rowsums and persisted.
// =================================================================
template<bool FIRST>
__global__ __launch_bounds__(256, 8) void reduce_k(
    const float* __restrict__ part,
    const float* __restrict__ bias,
    float* __restrict__ invd,
    const float* __restrict__ rs,
    float* __restrict__ out)
{
    const size_t base = ((size_t)blockIdx.x * 256 + threadIdx.x) * 4;
    const int f0 = (int)(base & 127);
    const size_t tg = base >> 7;     // b*NN + token

    float inv;
    if (FIRST) {
        inv = 1.0f / (rs[tg] + rs[(size_t)BB * NN + tg] + 1.0f);
        if (f0 == 0) invd[tg] = inv;
    } else {
        inv = invd[tg];
    }

    float4 p0 = *reinterpret_cast<const float4*>(part + base);
    float4 p1 = *reinterpret_cast<const float4*>(part + (size_t)BB * NN * DD + base);
    float4 bv = *reinterpret_cast<const float4*>(bias + f0);
    float4 o;
    o.x = fmaxf((p0.x + p1.x + bv.x) * inv, 0.f);
    o.y = fmaxf((p0.y + p1.y + bv.y) * inv, 0.f);
    o.z = fmaxf((p0.z + p1.z + bv.z) * inv, 0.f);
    o.w = fmaxf((p0.w + p1.w + bv.w) * inv, 0.f);
    *reinterpret_cast<float4*>(out + base) = o;
}

// =================================================================
extern "C" void kernel_launch(void* const* d_in, const int* in_sizes, int n_in,
                              void* d_out, int out_size)
{
    const float *inputs = nullptr, *adj = nullptr, *W = nullptr, *bias = nullptr;
    for (int i = 0; i < n_in; i++) {
        const long long s = in_sizes[i];
        if      (s == (long long)BB * NN * DD) inputs = (const float*)d_in[i];
        else if (s == (long long)BB * NN * NN) adj    = (const float*)d_in[i];
        else if (s == 3LL * DD * DD)           W      = (const float*)d_in[i];
        else if (s == 3LL * DD)                bias   = (const float*)d_in[i];
    }
    float* out = (float*)d_out;

    float *zp, *x, *part, *rs, *invd;
    cudaGetSymbolAddress((void**)&zp,   g_zp);
    cudaGetSymbolAddress((void**)&x,    g_x);
    cudaGetSymbolAddress((void**)&part, g_part);
    cudaGetSymbolAddress((void**)&rs,   g_rs);
    cudaGetSymbolAddress((void**)&invd, g_invden);

    static bool attr_done = false;
    if (!attr_done) {
        cudaFuncSetAttribute(gk<32, true,  true,  false>, cudaFuncAttributeMaxDynamicSharedMemorySize, SMEM_T);
        cudaFuncSetAttribute(gk<32, true,  false, false>, cudaFuncAttributeMaxDynamicSharedMemorySize, SMEM_T);
        cudaFuncSetAttribute(gk<4,  false, false, true >, cudaFuncAttributeMaxDynamicSharedMemorySize, SMEM_T);
        attr_done = true;
    }

    const dim3 gAX(NN / 128, BB, 2);        // 16 x 8 x 2 = 256 CTAs (split-K)
    const dim3 gZK((BB * NN) / 128, 1, 1);  // 128 CTAs
    const int gRED = (BB * NN * DD) / 1024; // 2048 CTAs

    // layer 0
    gk<4, false, false, true ><<<gZK, 256, SMEM_T>>>(inputs, DD, W, zp, nullptr);
    gk<32, true, true,  false><<<gAX, 256, SMEM_T>>>(adj, NN, zp, part, rs);
    reduce_k<true ><<<gRED, 256>>>(part, bias, invd, rs, x);
    // layer 1
    gk<4, false, false, true ><<<gZK, 256, SMEM_T>>>(x, DD, W + DD * DD, zp, nullptr);
    gk<32, true, false, false><<<gAX, 256, SMEM_T>>>(adj, NN, zp, part, nullptr);
    reduce_k<false><<<gRED, 256>>>(part, bias + DD, invd, nullptr, x);
    // layer 2
    gk<4, false, false, true ><<<gZK, 256, SMEM_T>>>(x, DD, W + 2 * DD * DD, zp, nullptr);
    gk<32, true, false, false><<<gAX, 256, SMEM_T>>>(adj, NN, zp, part, nullptr);
    reduce_k<false><<<gRED, 256>>>(part, bias + 2 * DD, invd, nullptr, out);
}

// round 7
// speedup vs baseline: 2.2228x; 1.5051x over previous
#include <cuda_runtime.h>
#include <cuda_fp16.h>
#include <cstdint>
#include <cstddef>

#define BB 8
#define NN 2048
#define DD 128

// ---------------- scratch (no allocs allowed) ----------------
__device__ float g_zp  [BB * NN * DD];        // Z fp16 frag-packed (uses half the bytes)
__device__ float g_x   [BB * NN * DD];        // activations [b][token][feat]
__device__ float g_part[2 * BB * NN * DD];    // split-K partials
__device__ float g_rs  [2 * BB * NN];         // split-K partial rowsums (layer 0)
__device__ float g_invden[BB * NN];

typedef unsigned long long u64;

// ---------------- PTX helpers ----------------
__device__ __forceinline__ uint32_t smem_u32(const void* p) {
    uint32_t a;
    asm("{ .reg .u64 t; cvta.to.shared.u64 t, %1; cvt.u32.u64 %0, t; }" : "=r"(a) : "l"(p));
    return a;
}
__device__ __forceinline__ void cp16(uint32_t dst, const void* src) {
    asm volatile("cp.async.cg.shared.global [%0], [%1], 16;" :: "r"(dst), "l"(src));
}
__device__ __forceinline__ void cp_commit() {
    asm volatile("cp.async.commit_group;" ::: "memory");
}
__device__ __forceinline__ uint32_t cvt_tf32(float x) {
    uint32_t r; asm("cvt.rna.tf32.f32 %0, %1;" : "=r"(r) : "f"(x)); return r;
}
// pack two f32 -> f16x2 reg: lo = 'lo' operand, hi = 'hi' operand
__device__ __forceinline__ uint32_t pkh(float lo, float hi) {
    uint32_t d;
    asm("cvt.rn.f16x2.f32 %0, %1, %2;" : "=r"(d) : "f"(hi), "f"(lo));
    return d;
}
// m16n8k8 tf32 HMMA (zk kernel)
__device__ __forceinline__ void mma_tf32(float* d,
    uint32_t a0, uint32_t a1, uint32_t a2, uint32_t a3,
    uint32_t b0, uint32_t b1)
{
    asm volatile(
        "mma.sync.aligned.m16n8k8.row.col.f32.tf32.tf32.f32 "
        "{%0,%1,%2,%3}, {%4,%5,%6,%7}, {%8,%9}, {%0,%1,%2,%3};"
        : "+f"(d[0]), "+f"(d[1]), "+f"(d[2]), "+f"(d[3])
        : "r"(a0), "r"(a1), "r"(a2), "r"(a3), "r"(b0), "r"(b1));
}
// m16n8k16 fp16 HMMA, fp32 accumulate (AX kernel)
__device__ __forceinline__ void mma_f16(float* d,
    uint32_t a0, uint32_t a1, uint32_t a2, uint32_t a3,
    uint32_t b0, uint32_t b1)
{
    asm volatile(
        "mma.sync.aligned.m16n8k16.row.col.f32.f16.f16.f32 "
        "{%0,%1,%2,%3}, {%4,%5,%6,%7}, {%8,%9}, {%0,%1,%2,%3};"
        : "+f"(d[0]), "+f"(d[1]), "+f"(d[2]), "+f"(d[3])
        : "r"(a0), "r"(a1), "r"(a2), "r"(a3), "r"(b0), "r"(b1));
}

// =================================================================
//  AX kernel (fp16 HMMA): partials of A @ Z, split-K x2.
//  A fp32 raw in smem (APAD=40 words/row -> LDS.64 frag pairs, then
//  cvt.rn.f16x2). Z fp16 pre-packed in exact B-fragment order:
//  [kstep16][col][16 halves interleaved (w0,w4,w1,w5,w2,w6,w3,w7)],
//  so one LDS.64 per (col,kstep) yields {b0,b1}.
//  CTA 128x128, 8 warps (32x64 each), BK=32, 3-stage cp.async, occ 2.
// =================================================================
#define APAD_AX 40
#define A_TB (128 * APAD_AX * 4)      // 20480
#define Z_TB 8192                     // 32k x 128col x 2B
#define STB_AX (A_TB + Z_TB)          // 28672
#define SMEM_AX (1024 + 3 * STB_AX)   // 87040
#define NCH_AX 32                     // 1024 k per split

template<bool FIRST>
__global__ __launch_bounds__(256, 2) void ax16(
    const float* __restrict__ A,
    const char* __restrict__ Zp,       // fp16 packed, 512KB per batch
    float* __restrict__ Pout,
    float* __restrict__ rsOut)
{
    extern __shared__ __align__(16) char sm[];
    const uint32_t smb = smem_u32(sm);

    const int tid = threadIdx.x, lane = tid & 31, wid = tid >> 5;
    const int b = blockIdx.y, z = blockIdx.z;
    const int m0 = blockIdx.x * 128;

    // A loader: 128 rows x 32 k, 2 thr/row
    const int arow = tid >> 1, ahalf = tid & 1;
    const float* aGlob = A + ((size_t)b * NN + m0 + arow) * NN + z * (NCH_AX * 32) + ahalf * 16;
    const uint32_t adst = (uint32_t)(arow * (APAD_AX * 4) + ahalf * 64);
    // Z loader: 8KB contiguous per chunk, 32B per thread
    const char* zGlob = Zp + (size_t)b * 524288 + (size_t)(z * 64) * 4096 + tid * 32;

    auto load_chunk = [&](int i) {
        const uint32_t base = smb + 1024 + (i % 3) * STB_AX;
        const float* sa = aGlob + i * 32;
        const uint32_t da = base + adst;
        cp16(da,      sa);      cp16(da + 16, sa + 4);
        cp16(da + 32, sa + 8);  cp16(da + 48, sa + 12);
        const char* sz = zGlob + (size_t)i * 8192;
        const uint32_t dz = base + A_TB + tid * 32;
        cp16(dz, sz);  cp16(dz + 16, sz + 16);
        cp_commit();
    };

    // compute mapping: warp grid 4(M) x 2(N), warp tile 32x64
    const int g = lane >> 2, c = lane & 3;
    const int wm = (wid & 3) * 32, wn = (wid >> 2) * 64;

    float acc[2][8][4];
    #pragma unroll
    for (int mi = 0; mi < 2; mi++)
        #pragma unroll
        for (int nj = 0; nj < 8; nj++)
            #pragma unroll
            for (int q = 0; q < 4; q++) acc[mi][nj][q] = 0.f;

    float rs = 0.f;

    load_chunk(0);
    load_chunk(1);

    #pragma unroll 1
    for (int i = 0; i < NCH_AX; i++) {
        if (i < NCH_AX - 2) { asm volatile("cp.async.wait_group 1;" ::: "memory"); }
        else                { asm volatile("cp.async.wait_group 0;" ::: "memory"); }
        __syncthreads();
        if (i < NCH_AX - 2) load_chunk(i + 2);

        const float* As = reinterpret_cast<const float*>(sm + 1024 + (i % 3) * STB_AX);
        const char*  Bs = reinterpret_cast<const char*>(As) + A_TB;

        if (FIRST) {   // partial rowsum of A chunk from smem
            const float4* ar = reinterpret_cast<const float4*>(As + arow * APAD_AX + ahalf * 16);
            float4 v0 = ar[0], v1 = ar[1], v2 = ar[2], v3 = ar[3];
            rs += (v0.x + v0.y + v0.z + v0.w) + (v1.x + v1.y + v1.z + v1.w)
                + (v2.x + v2.y + v2.z + v2.w) + (v3.x + v3.y + v3.z + v3.w);
        }

        #pragma unroll
        for (int ks = 0; ks < 2; ks++) {
            const int kb = ks * 16 + 2 * c;
            uint32_t a[2][4];
            #pragma unroll
            for (int mi = 0; mi < 2; mi++) {
                const int rlo = wm + 16 * mi + g, rhi = rlo + 8;
                float2 f0 = *reinterpret_cast<const float2*>(As + rlo * APAD_AX + kb);
                float2 f1 = *reinterpret_cast<const float2*>(As + rhi * APAD_AX + kb);
                float2 f2 = *reinterpret_cast<const float2*>(As + rlo * APAD_AX + kb + 8);
                float2 f3 = *reinterpret_cast<const float2*>(As + rhi * APAD_AX + kb + 8);
                a[mi][0] = pkh(f0.x, f0.y);
                a[mi][1] = pkh(f1.x, f1.y);
                a[mi][2] = pkh(f2.x, f2.y);
                a[mi][3] = pkh(f3.x, f3.y);
            }
            #pragma unroll
            for (int nj = 0; nj < 8; nj++) {
                const int col = wn + 8 * nj + g;
                uint2 bb = *reinterpret_cast<const uint2*>(Bs + ks * 4096 + col * 32 + c * 8);
                mma_f16(acc[0][nj], a[0][0], a[0][1], a[0][2], a[0][3], bb.x, bb.y);
                mma_f16(acc[1][nj], a[1][0], a[1][1], a[1][2], a[1][3], bb.x, bb.y);
            }
        }
    }

    if (FIRST) {
        float stot = rs + __shfl_xor_sync(0xffffffffu, rs, 1);   // tid^1 shares arow
        if (ahalf == 0)
            rsOut[(size_t)(z * BB + b) * NN + m0 + arow] = stot;
    }

    // raw split-K partials
    float* pb = Pout + (size_t)(z * BB + b) * NN * DD;
    #pragma unroll
    for (int mi = 0; mi < 2; mi++) {
        const int r_lo = wm + 16 * mi + g;
        float* o_lo = pb + (size_t)(m0 + r_lo) * DD;
        float* o_hi = pb + (size_t)(m0 + r_lo + 8) * DD;
        #pragma unroll
        for (int nj = 0; nj < 8; nj++) {
            const int col = wn + 8 * nj + 2 * c;
            *reinterpret_cast<float2*>(o_lo + col) = make_float2(acc[mi][nj][0], acc[mi][nj][1]);
            *reinterpret_cast<float2*>(o_hi + col) = make_float2(acc[mi][nj][2], acc[mi][nj][3]);
        }
    }
}

// =================================================================
//  zk kernel (tf32 HMMA): Z = X @ W; epilogue packs fp16 Z in the
//  AX B-fragment layout via smem repack, then coalesced uint4 out.
//  CTA 128 tokens x 128 feats, K=128 (4 chunks), occ 2.
// =================================================================
#define APAD_ZK 36
#define WPAD   136
#define AZ_TB (128 * APAD_ZK * 4)     // 18432
#define W_TB  (32 * WPAD * 4)         // 17408
#define STB_ZK (AZ_TB + W_TB)         // 35840
#define SMEM_ZK (1024 + 3 * STB_ZK)   // 108544

__global__ __launch_bounds__(256, 2) void zk_t(
    const float* __restrict__ X,
    const float* __restrict__ W,
    char* __restrict__ Zp)
{
    extern __shared__ __align__(16) char sm[];
    const uint32_t smb = smem_u32(sm);

    const int tid = threadIdx.x, lane = tid & 31, wid = tid >> 5;
    const int m0 = blockIdx.x * 128;                 // global token tile

    const int arow = tid >> 1, ahalf = tid & 1;
    const float* aGlob = X + (size_t)(m0 + arow) * DD + ahalf * 16;
    const uint32_t adst = (uint32_t)(arow * (APAD_ZK * 4) + ahalf * 64);
    const int wkr = tid >> 3, wkc = (tid & 7) * 16;
    const float* wGlob = W + (size_t)wkr * DD + wkc;
    const uint32_t wdst = (uint32_t)(AZ_TB + wkr * (WPAD * 4) + wkc * 4);

    auto load_chunk = [&](int i) {
        const uint32_t base = smb + 1024 + (i % 3) * STB_ZK;
        const float* sa = aGlob + i * 32;
        const uint32_t da = base + adst;
        cp16(da,      sa);      cp16(da + 16, sa + 4);
        cp16(da + 32, sa + 8);  cp16(da + 48, sa + 12);
        const float* sw = wGlob + (size_t)i * 32 * DD;
        const uint32_t dw = base + wdst;
        cp16(dw,      sw);      cp16(dw + 16, sw + 4);
        cp16(dw + 32, sw + 8);  cp16(dw + 48, sw + 12);
        cp_commit();
    };

    const int g = lane >> 2, c = lane & 3;
    const int wm = (wid & 3) * 32, wn = (wid >> 2) * 64;

    float acc[2][8][4];
    #pragma unroll
    for (int mi = 0; mi < 2; mi++)
        #pragma unroll
        for (int nj = 0; nj < 8; nj++)
            #pragma unroll
            for (int q = 0; q < 4; q++) acc[mi][nj][q] = 0.f;

    load_chunk(0);
    load_chunk(1);

    #pragma unroll 1
    for (int i = 0; i < 4; i++) {
        if (i < 2) { asm volatile("cp.async.wait_group 1;" ::: "memory"); }
        else       { asm volatile("cp.async.wait_group 0;" ::: "memory"); }
        __syncthreads();
        if (i < 2) load_chunk(i + 2);

        const float* As = reinterpret_cast<const float*>(sm + 1024 + (i % 3) * STB_ZK);
        const uint32_t* Wu = reinterpret_cast<const uint32_t*>(As + AZ_TB / 4);

        #pragma unroll
        for (int ks = 0; ks < 4; ks++) {
            const int kk = ks * 8 + c;
            uint32_t a0[4], a1[4];
            a0[0] = cvt_tf32(As[(wm + g)      * APAD_ZK + kk]);
            a0[1] = cvt_tf32(As[(wm + g + 8)  * APAD_ZK + kk]);
            a0[2] = cvt_tf32(As[(wm + g)      * APAD_ZK + kk + 4]);
            a0[3] = cvt_tf32(As[(wm + g + 8)  * APAD_ZK + kk + 4]);
            a1[0] = cvt_tf32(As[(wm + 16 + g) * APAD_ZK + kk]);
            a1[1] = cvt_tf32(As[(wm + 24 + g) * APAD_ZK + kk]);
            a1[2] = cvt_tf32(As[(wm + 16 + g) * APAD_ZK + kk + 4]);
            a1[3] = cvt_tf32(As[(wm + 24 + g) * APAD_ZK + kk + 4]);
            #pragma unroll
            for (int nj = 0; nj < 8; nj++) {
                const int col = wn + 8 * nj + g;
                uint32_t b0 = cvt_tf32(__uint_as_float(Wu[kk       * WPAD + col]));
                uint32_t b1 = cvt_tf32(__uint_as_float(Wu[(kk + 4) * WPAD + col]));
                mma_tf32(acc[0][nj], a0[0], a0[1], a0[2], a0[3], b0, b1);
                mma_tf32(acc[1][nj], a1[0], a1[1], a1[2], a1[3], b0, b1);
            }
        }
    }

    // ---- epilogue: fp16 frag-pack via smem, then coalesced copy ----
    __syncthreads();                              // stage reads done
    __half* hb = reinterpret_cast<__half*>(sm + 1024);   // 32 KB overlay
    #pragma unroll
    for (int mi = 0; mi < 2; mi++) {
        #pragma unroll
        for (int q = 0; q < 4; q++) {
            const int tl = wm + 16 * mi + g + 8 * (q >> 1);   // local token
            const int ksl = tl >> 4;
            const int j = (tl & 15) >> 1, e = tl & 1;
            const int swd = (j < 4) ? (2 * j) : (2 * (j - 4) + 1);
            const int p = 2 * swd + e;
            #pragma unroll
            for (int nj = 0; nj < 8; nj++) {
                const int col = wn + 8 * nj + 2 * c + (q & 1);
                hb[(ksl * 128 + col) * 16 + p] = __float2half(acc[mi][nj][q]);
            }
        }
    }
    __syncthreads();
    const int zb = m0 >> 11, mloc = m0 & 2047;
    char* dst = Zp + (size_t)zb * 524288 + (size_t)(mloc >> 4) * 4096;
    const uint4* src = reinterpret_cast<const uint4*>(hb);
    #pragma unroll
    for (int i = tid; i < 2048; i += 256)
        reinterpret_cast<uint4*>(dst)[i] = src[i];
}

// =================================================================
//  Reduce: out = relu((p0 + p1 + bias) * invden); FIRST builds invden.
// =================================================================
template<bool FIRST>
__global__ __launch_bounds__(256, 8) void reduce_k(
    const float* __restrict__ part,
    const float* __restrict__ bias,
    float* __restrict__ invd,
    const float* __restrict__ rs,
    float* __restrict__ out)
{
    const size_t base = ((size_t)blockIdx.x * 256 + threadIdx.x) * 4;
    const int f0 = (int)(base & 127);
    const size_t tg = base >> 7;

    float inv;
    if (FIRST) {
        inv = 1.0f / (rs[tg] + rs[(size_t)BB * NN + tg] + 1.0f);
        if (f0 == 0) invd[tg] = inv;
    } else {
        inv = invd[tg];
    }

    float4 p0 = *reinterpret_cast<const float4*>(part + base);
    float4 p1 = *reinterpret_cast<const float4*>(part + (size_t)BB * NN * DD + base);
    float4 bv = *reinterpret_cast<const float4*>(bias + f0);
    float4 o;
    o.x = fmaxf((p0.x + p1.x + bv.x) * inv, 0.f);
    o.y = fmaxf((p0.y + p1.y + bv.y) * inv, 0.f);
    o.z = fmaxf((p0.z + p1.z + bv.z) * inv, 0.f);
    o.w = fmaxf((p0.w + p1.w + bv.w) * inv, 0.f);
    *reinterpret_cast<float4*>(out + base) = o;
}

// =================================================================
extern "C" void kernel_launch(void* const* d_in, const int* in_sizes, int n_in,
                              void* d_out, int out_size)
{
    const float *inputs = nullptr, *adj = nullptr, *W = nullptr, *bias = nullptr;
    for (int i = 0; i < n_in; i++) {
        const long long s = in_sizes[i];
        if      (s == (long long)BB * NN * DD) inputs = (const float*)d_in[i];
        else if (s == (long long)BB * NN * NN) adj    = (const float*)d_in[i];
        else if (s == 3LL * DD * DD)           W      = (const float*)d_in[i];
        else if (s == 3LL * DD)                bias   = (const float*)d_in[i];
    }
    float* out = (float*)d_out;

    float *zpf, *x, *part, *rs, *invd;
    cudaGetSymbolAddress((void**)&zpf,  g_zp);
    cudaGetSymbolAddress((void**)&x,    g_x);
    cudaGetSymbolAddress((void**)&part, g_part);
    cudaGetSymbolAddress((void**)&rs,   g_rs);
    cudaGetSymbolAddress((void**)&invd, g_invden);
    char* zp = reinterpret_cast<char*>(zpf);

    static bool attr_done = false;
    if (!attr_done) {
        cudaFuncSetAttribute(ax16<true>,  cudaFuncAttributeMaxDynamicSharedMemorySize, SMEM_AX);
        cudaFuncSetAttribute(ax16<false>, cudaFuncAttributeMaxDynamicSharedMemorySize, SMEM_AX);
        cudaFuncSetAttribute(zk_t,        cudaFuncAttributeMaxDynamicSharedMemorySize, SMEM_ZK);
        attr_done = true;
    }

    const dim3 gAX(NN / 128, BB, 2);        // 256 CTAs (split-K x2)
    const dim3 gZK((BB * NN) / 128, 1, 1);  // 128 CTAs
    const int gRED = (BB * NN * DD) / 1024; // 2048 CTAs

    // layer 0
    zk_t<<<gZK, 256, SMEM_ZK>>>(inputs, W, zp);
    ax16<true ><<<gAX, 256, SMEM_AX>>>(adj, zp, part, rs);
    reduce_k<true ><<<gRED, 256>>>(part, bias, invd, rs, x);
    // layer 1
    zk_t<<<gZK, 256, SMEM_ZK>>>(x, W + DD * DD, zp);
    ax16<false><<<gAX, 256, SMEM_AX>>>(adj, zp, part, nullptr);
    reduce_k<false><<<gRED, 256>>>(part, bias + DD, invd, nullptr, x);
    // layer 2
    zk_t<<<gZK, 256, SMEM_ZK>>>(x, W + 2 * DD * DD, zp);
    ax16<false><<<gAX, 256, SMEM_AX>>>(adj, zp, part, nullptr);
    reduce_k<false><<<gRED, 256>>>(part, bias + 2 * DD, invd, nullptr, out);
}

// round 9
// speedup vs baseline: 2.4679x; 1.1103x over previous
#include <cuda_runtime.h>
#include <cuda_fp16.h>
#include <cstdint>
#include <cstddef>

#define BB 8
#define NN 2048
#define DD 128
#define NCH 32

// ---------------- scratch (no allocs allowed) ----------------
__device__ __half g_a16[(size_t)BB * NN * NN];   // 67MB frag-packed fp16 A
__device__ __half g_zpk[BB * NN * DD];           // 4MB packed fp16 Z
__device__ float  g_part[2 * BB * NN * DD];      // split-K partials (16MB)
__device__ float  g_rs  [2 * BB * NN];           // partial rowsums (layer 0)
__device__ float  g_invden[BB * NN];

typedef unsigned long long u64;

// ---------------- PTX helpers ----------------
__device__ __forceinline__ uint32_t smem_u32(const void* p) {
    uint32_t a;
    asm("{ .reg .u64 t; cvta.to.shared.u64 t, %1; cvt.u32.u64 %0, t; }" : "=r"(a) : "l"(p));
    return a;
}
__device__ __forceinline__ void cp16(uint32_t dst, const void* src) {
    asm volatile("cp.async.cg.shared.global [%0], [%1], 16;" :: "r"(dst), "l"(src));
}
__device__ __forceinline__ void cp_commit() {
    asm volatile("cp.async.commit_group;" ::: "memory");
}
__device__ __forceinline__ uint32_t cvt_tf32(float x) {
    uint32_t r; asm("cvt.rna.tf32.f32 %0, %1;" : "=r"(r) : "f"(x)); return r;
}
__device__ __forceinline__ uint32_t pkh(float lo, float hi) {
    uint32_t d;
    asm("cvt.rn.f16x2.f32 %0, %1, %2;" : "=r"(d) : "f"(hi), "f"(lo));
    return d;
}
__device__ __forceinline__ void mma_tf32(float* d,
    uint32_t a0, uint32_t a1, uint32_t a2, uint32_t a3, uint32_t b0, uint32_t b1)
{
    asm volatile(
        "mma.sync.aligned.m16n8k8.row.col.f32.tf32.tf32.f32 "
        "{%0,%1,%2,%3}, {%4,%5,%6,%7}, {%8,%9}, {%0,%1,%2,%3};"
        : "+f"(d[0]), "+f"(d[1]), "+f"(d[2]), "+f"(d[3])
        : "r"(a0), "r"(a1), "r"(a2), "r"(a3), "r"(b0), "r"(b1));
}
__device__ __forceinline__ void mma_f16(float* d,
    uint32_t a0, uint32_t a1, uint32_t a2, uint32_t a3, uint32_t b0, uint32_t b1)
{
    asm volatile(
        "mma.sync.aligned.m16n8k16.row.col.f32.f16.f16.f32 "
        "{%0,%1,%2,%3}, {%4,%5,%6,%7}, {%8,%9}, {%0,%1,%2,%3};"
        : "+f"(d[0]), "+f"(d[1]), "+f"(d[2]), "+f"(d[3])
        : "r"(a0), "r"(a1), "r"(a2), "r"(a3), "r"(b0), "r"(b1));
}

// =================================================================
//  Layout notes
//  A16 [b][ks16 0..127][row 0..2047][16 halves]: within 32B, half p = c*4+h*2+e
//     holds k-offset kl = 2c+8h+e  ->  LDS.64 at c*8B = (a0pair, a2pair).
//  Zpk [b][kp=t/32 0..63][n 0..127][32 halves]: half = c*8 + ks*4 + h*2 + e
//     (token kl = 2c+8h+e within ks16 half of kp block)
//     -> LDS.128 at n*64B + c*16B = {b0,b1 (ks0), b0,b1 (ks1)}.
// =================================================================

// =================================================================
//  ax_first: layer-0 A@Z. A fp32 in, fp16 frag-packed A16 out
//  (side product) + partial rowsums. Split-K x2, 3-stage, occ 2.
// =================================================================
#define APAD_AX 40
#define A_TB (128 * APAD_AX * 4)      // 20480
#define Z_TB 8192
#define STB0 (A_TB + Z_TB)            // 28672
#define SMEM_AX0 (1024 + 3 * STB0)    // 87040

__global__ __launch_bounds__(256, 2) void ax_first(
    const float* __restrict__ A, const __half* __restrict__ Zp,
    float* __restrict__ Pout, float* __restrict__ rsOut,
    __half* __restrict__ A16)
{
    extern __shared__ __align__(16) char sm[];
    const uint32_t smb = smem_u32(sm);
    const int tid = threadIdx.x, lane = tid & 31, wid = tid >> 5;
    const int b = blockIdx.y, z = blockIdx.z, m0 = blockIdx.x * 128;

    const int arow = tid >> 1, ahalf = tid & 1;
    const float* aGlob = A + ((size_t)b * NN + m0 + arow) * NN + z * (NCH * 32) + ahalf * 16;
    const uint32_t adst = (uint32_t)(arow * (APAD_AX * 4) + ahalf * 64);
    const __half* zGlob = Zp + (size_t)b * NN * DD + (size_t)(z * 32) * 4096 + tid * 16;

    auto load_chunk = [&](int i) {
        const uint32_t base = smb + 1024 + (i % 3) * STB0;
        const float* sa = aGlob + i * 32;
        const uint32_t da = base + adst;
        cp16(da,      sa);      cp16(da + 16, sa + 4);
        cp16(da + 32, sa + 8);  cp16(da + 48, sa + 12);
        const __half* sz = zGlob + (size_t)i * 4096;
        const uint32_t dz = base + A_TB + tid * 32;
        cp16(dz, sz);  cp16(dz + 16, sz + 8);
        cp_commit();
    };

    const int g = lane >> 2, c = lane & 3;
    const int wm = (wid & 3) * 32, wn = (wid >> 2) * 64;

    float acc[2][8][4];
    #pragma unroll
    for (int mi = 0; mi < 2; mi++)
        #pragma unroll
        for (int nj = 0; nj < 8; nj++)
            #pragma unroll
            for (int q = 0; q < 4; q++) acc[mi][nj][q] = 0.f;

    float rsum = 0.f;

    load_chunk(0);
    load_chunk(1);

    #pragma unroll 1
    for (int i = 0; i < NCH; i++) {
        if (i < NCH - 2) { asm volatile("cp.async.wait_group 1;" ::: "memory"); }
        else             { asm volatile("cp.async.wait_group 0;" ::: "memory"); }
        __syncthreads();
        if (i < NCH - 2) load_chunk(i + 2);

        const float* As = reinterpret_cast<const float*>(sm + 1024 + (i % 3) * STB0);
        const __half* Bs = reinterpret_cast<const __half*>(
            reinterpret_cast<const char*>(As) + A_TB);

        // rowsum + A16 side write (from smem, 16 k of one ks16 per thread)
        {
            const float4* ar = reinterpret_cast<const float4*>(As + arow * APAD_AX + ahalf * 16);
            float4 v0 = ar[0], v1 = ar[1], v2 = ar[2], v3 = ar[3];
            rsum += (v0.x + v0.y + v0.z + v0.w) + (v1.x + v1.y + v1.z + v1.w)
                  + (v2.x + v2.y + v2.z + v2.w) + (v3.x + v3.y + v3.z + v3.w);
            uint4 w0, w1;
            w0.x = pkh(v0.x, v0.y);  w0.y = pkh(v2.x, v2.y);
            w0.z = pkh(v0.z, v0.w);  w0.w = pkh(v2.z, v2.w);
            w1.x = pkh(v1.x, v1.y);  w1.y = pkh(v3.x, v3.y);
            w1.z = pkh(v1.z, v1.w);  w1.w = pkh(v3.z, v3.w);
            const size_t ks = (size_t)(b * 128 + z * 64 + 2 * i + ahalf);
            uint4* dst = reinterpret_cast<uint4*>(A16 + (ks * NN + m0 + arow) * 16);
            dst[0] = w0;  dst[1] = w1;
        }

        uint32_t af[2][2][4];
        #pragma unroll
        for (int ks = 0; ks < 2; ks++)
            #pragma unroll
            for (int mi = 0; mi < 2; mi++) {
                const int rlo = wm + 16 * mi + g, rhi = rlo + 8;
                const int kb = ks * 16 + 2 * c;
                float2 f0 = *reinterpret_cast<const float2*>(As + rlo * APAD_AX + kb);
                float2 f1 = *reinterpret_cast<const float2*>(As + rhi * APAD_AX + kb);
                float2 f2 = *reinterpret_cast<const float2*>(As + rlo * APAD_AX + kb + 8);
                float2 f3 = *reinterpret_cast<const float2*>(As + rhi * APAD_AX + kb + 8);
                af[ks][mi][0] = pkh(f0.x, f0.y);
                af[ks][mi][1] = pkh(f1.x, f1.y);
                af[ks][mi][2] = pkh(f2.x, f2.y);
                af[ks][mi][3] = pkh(f3.x, f3.y);
            }
        #pragma unroll
        for (int nj = 0; nj < 8; nj++) {
            const int col = wn + 8 * nj + g;
            uint4 bb = *reinterpret_cast<const uint4*>(Bs + col * 32 + c * 8);
            mma_f16(acc[0][nj], af[0][0][0], af[0][0][1], af[0][0][2], af[0][0][3], bb.x, bb.y);
            mma_f16(acc[1][nj], af[0][1][0], af[0][1][1], af[0][1][2], af[0][1][3], bb.x, bb.y);
            mma_f16(acc[0][nj], af[1][0][0], af[1][0][1], af[1][0][2], af[1][0][3], bb.z, bb.w);
            mma_f16(acc[1][nj], af[1][1][0], af[1][1][1], af[1][1][2], af[1][1][3], bb.z, bb.w);
        }
    }

    {
        float stot = rsum + __shfl_xor_sync(0xffffffffu, rsum, 1);  // tid^1 shares arow
        if (ahalf == 0)
            rsOut[(size_t)(z * BB + b) * NN + m0 + arow] = stot;
    }

    float* pb = Pout + (size_t)(z * BB + b) * NN * DD;
    #pragma unroll
    for (int mi = 0; mi < 2; mi++) {
        const int r_lo = wm + 16 * mi + g;
        float* o_lo = pb + (size_t)(m0 + r_lo) * DD;
        float* o_hi = pb + (size_t)(m0 + r_lo + 8) * DD;
        #pragma unroll
        for (int nj = 0; nj < 8; nj++) {
            const int col = wn + 8 * nj + 2 * c;
            *reinterpret_cast<float2*>(o_lo + col) = make_float2(acc[mi][nj][0], acc[mi][nj][1]);
            *reinterpret_cast<float2*>(o_hi + col) = make_float2(acc[mi][nj][2], acc[mi][nj][3]);
        }
    }
}

// =================================================================
//  ax_rest: layers 1/2 A16@Z. Both operands fp16 pre-packed.
//  16KB stages, 4-deep pipeline, occ 2, split-K x2.
// =================================================================
#define STB12 16384
#define SMEM_AX12 (1024 + 4 * STB12)   // 66560

__global__ __launch_bounds__(256, 2) void ax_rest(
    const __half* __restrict__ A16, const __half* __restrict__ Zp,
    float* __restrict__ Pout)
{
    extern __shared__ __align__(16) char sm[];
    const uint32_t smb = smem_u32(sm);
    const int tid = threadIdx.x, lane = tid & 31, wid = tid >> 5;
    const int b = blockIdx.y, z = blockIdx.z, m0 = blockIdx.x * 128;

    const int arow = tid >> 1, ahalf = tid & 1;
    const __half* aGlob = A16 + ((size_t)(b * 128 + z * 64 + ahalf) * NN + m0 + arow) * 16;
    const __half* zGlob = Zp + (size_t)b * NN * DD + (size_t)(z * 32) * 4096 + tid * 16;
    const uint32_t adst = (uint32_t)(ahalf * 4096 + arow * 32);

    auto load_chunk = [&](int i) {
        const uint32_t base = smb + 1024 + (i & 3) * STB12;
        const __half* sa = aGlob + (size_t)(2 * i) * NN * 16;
        const uint32_t da = base + adst;
        cp16(da, sa);  cp16(da + 16, sa + 8);
        const __half* sz = zGlob + (size_t)i * 4096;
        const uint32_t dz = base + 8192 + tid * 32;
        cp16(dz, sz);  cp16(dz + 16, sz + 8);
        cp_commit();
    };

    const int g = lane >> 2, c = lane & 3;
    const int wm = (wid & 3) * 32, wn = (wid >> 2) * 64;

    float acc[2][8][4];
    #pragma unroll
    for (int mi = 0; mi < 2; mi++)
        #pragma unroll
        for (int nj = 0; nj < 8; nj++)
            #pragma unroll
            for (int q = 0; q < 4; q++) acc[mi][nj][q] = 0.f;

    load_chunk(0);
    load_chunk(1);
    load_chunk(2);

    #pragma unroll 1
    for (int i = 0; i < NCH; i++) {
        if (i < NCH - 2)       { asm volatile("cp.async.wait_group 2;" ::: "memory"); }
        else if (i == NCH - 2) { asm volatile("cp.async.wait_group 1;" ::: "memory"); }
        else                   { asm volatile("cp.async.wait_group 0;" ::: "memory"); }
        __syncthreads();
        if (i < NCH - 3) load_chunk(i + 3);

        const __half* As = reinterpret_cast<const __half*>(sm + 1024 + (i & 3) * STB12);
        const __half* Bs = As + 4096;

        uint32_t af[2][2][4];
        #pragma unroll
        for (int ks = 0; ks < 2; ks++)
            #pragma unroll
            for (int mi = 0; mi < 2; mi++) {
                const int rlo = wm + 16 * mi + g;
                uint2 u = *reinterpret_cast<const uint2*>(As + ks * 2048 + rlo * 16 + c * 4);
                uint2 v = *reinterpret_cast<const uint2*>(As + ks * 2048 + (rlo + 8) * 16 + c * 4);
                af[ks][mi][0] = u.x;  af[ks][mi][1] = v.x;
                af[ks][mi][2] = u.y;  af[ks][mi][3] = v.y;
            }
        #pragma unroll
        for (int nj = 0; nj < 8; nj++) {
            const int col = wn + 8 * nj + g;
            uint4 bb = *reinterpret_cast<const uint4*>(Bs + col * 32 + c * 8);
            mma_f16(acc[0][nj], af[0][0][0], af[0][0][1], af[0][0][2], af[0][0][3], bb.x, bb.y);
            mma_f16(acc[1][nj], af[0][1][0], af[0][1][1], af[0][1][2], af[0][1][3], bb.x, bb.y);
            mma_f16(acc[0][nj], af[1][0][0], af[1][0][1], af[1][0][2], af[1][0][3], bb.z, bb.w);
            mma_f16(acc[1][nj], af[1][1][0], af[1][1][1], af[1][1][2], af[1][1][3], bb.z, bb.w);
        }
    }

    float* pb = Pout + (size_t)(z * BB + b) * NN * DD;
    #pragma unroll
    for (int mi = 0; mi < 2; mi++) {
        const int r_lo = wm + 16 * mi + g;
        float* o_lo = pb + (size_t)(m0 + r_lo) * DD;
        float* o_hi = pb + (size_t)(m0 + r_lo + 8) * DD;
        #pragma unroll
        for (int nj = 0; nj < 8; nj++) {
            const int col = wn + 8 * nj + 2 * c;
            *reinterpret_cast<float2*>(o_lo + col) = make_float2(acc[mi][nj][0], acc[mi][nj][1]);
            *reinterpret_cast<float2*>(o_hi + col) = make_float2(acc[mi][nj][2], acc[mi][nj][3]);
        }
    }
}

// =================================================================
//  Z-pack epilogue helper (shared by zk_t and fused_rz)
// =================================================================
__device__ __forceinline__ void zpack_store(
    __half* hb, const float acc[2][8][4],
    int wm, int wn, int g, int c)
{
    #pragma unroll
    for (int mi = 0; mi < 2; mi++)
        #pragma unroll
        for (int q = 0; q < 4; q++)
            #pragma unroll
            for (int nj = 0; nj < 8; nj++) {
                const int t = wm + 16 * mi + g + 8 * (q >> 1);
                const int n = wn + 8 * nj + 2 * c + (q & 1);
                const int kl = t & 15, e = kl & 1, xx = kl >> 1;
                const int idx = (t >> 5) * 4096 + n * 32
                              + (xx & 3) * 8 + ((t >> 4) & 1) * 4 + (xx >> 2) * 2 + e;
                hb[idx] = __float2half(acc[mi][nj][q]);
            }
}

// =================================================================
//  zk_t (layer 0): Z = X @ W0, tf32 mainloop, packed-fp16 epilogue.
// =================================================================
#define APAD_ZK 36
#define WPAD   136
#define AZ_TB (128 * APAD_ZK * 4)     // 18432
#define W_TB  (32 * WPAD * 4)         // 17408
#define STB_ZK (AZ_TB + W_TB)
#define SMEM_ZK (1024 + 3 * STB_ZK)   // 108544

__global__ __launch_bounds__(256, 2) void zk_t(
    const float* __restrict__ X,
    const float* __restrict__ W,
    __half* __restrict__ Zp)
{
    extern __shared__ __align__(16) char sm[];
    const uint32_t smb = smem_u32(sm);
    const int tid = threadIdx.x, lane = tid & 31, wid = tid >> 5;
    const int m0 = blockIdx.x * 128;

    const int arow = tid >> 1, ahalf = tid & 1;
    const float* aGlob = X + (size_t)(m0 + arow) * DD + ahalf * 16;
    const uint32_t adst = (uint32_t)(arow * (APAD_ZK * 4) + ahalf * 64);
    const int wkr = tid >> 3, wkc = (tid & 7) * 16;
    const float* wGlob = W + (size_t)wkr * DD + wkc;
    const uint32_t wdst = (uint32_t)(AZ_TB + wkr * (WPAD * 4) + wkc * 4);

    auto load_chunk = [&](int i) {
        const uint32_t base = smb + 1024 + (i % 3) * STB_ZK;
        const float* sa = aGlob + i * 32;
        const uint32_t da = base + adst;
        cp16(da,      sa);      cp16(da + 16, sa + 4);
        cp16(da + 32, sa + 8);  cp16(da + 48, sa + 12);
        const float* sw = wGlob + (size_t)i * 32 * DD;
        const uint32_t dw = base + wdst;
        cp16(dw,      sw);      cp16(dw + 16, sw + 4);
        cp16(dw + 32, sw + 8);  cp16(dw + 48, sw + 12);
        cp_commit();
    };

    const int g = lane >> 2, c = lane & 3;
    const int wm = (wid & 3) * 32, wn = (wid >> 2) * 64;

    float acc[2][8][4];
    #pragma unroll
    for (int mi = 0; mi < 2; mi++)
        #pragma unroll
        for (int nj = 0; nj < 8; nj++)
            #pragma unroll
            for (int q = 0; q < 4; q++) acc[mi][nj][q] = 0.f;

    load_chunk(0);
    load_chunk(1);

    #pragma unroll 1
    for (int i = 0; i < 4; i++) {
        if (i < 2) { asm volatile("cp.async.wait_group 1;" ::: "memory"); }
        else       { asm volatile("cp.async.wait_group 0;" ::: "memory"); }
        __syncthreads();
        if (i < 2) load_chunk(i + 2);

        const float* As = reinterpret_cast<const float*>(sm + 1024 + (i % 3) * STB_ZK);
        const uint32_t* Wu = reinterpret_cast<const uint32_t*>(As + AZ_TB / 4);

        #pragma unroll
        for (int ks = 0; ks < 4; ks++) {
            const int kk = ks * 8 + c;
            uint32_t a0[4], a1[4];
            a0[0] = cvt_tf32(As[(wm + g)      * APAD_ZK + kk]);
            a0[1] = cvt_tf32(As[(wm + g + 8)  * APAD_ZK + kk]);
            a0[2] = cvt_tf32(As[(wm + g)      * APAD_ZK + kk + 4]);
            a0[3] = cvt_tf32(As[(wm + g + 8)  * APAD_ZK + kk + 4]);
            a1[0] = cvt_tf32(As[(wm + 16 + g) * APAD_ZK + kk]);
            a1[1] = cvt_tf32(As[(wm + 24 + g) * APAD_ZK + kk]);
            a1[2] = cvt_tf32(As[(wm + 16 + g) * APAD_ZK + kk + 4]);
            a1[3] = cvt_tf32(As[(wm + 24 + g) * APAD_ZK + kk + 4]);
            #pragma unroll
            for (int nj = 0; nj < 8; nj++) {
                const int col = wn + 8 * nj + g;
                uint32_t b0 = cvt_tf32(__uint_as_float(Wu[kk       * WPAD + col]));
                uint32_t b1 = cvt_tf32(__uint_as_float(Wu[(kk + 4) * WPAD + col]));
                mma_tf32(acc[0][nj], a0[0], a0[1], a0[2], a0[3], b0, b1);
                mma_tf32(acc[1][nj], a1[0], a1[1], a1[2], a1[3], b0, b1);
            }
        }
    }

    __syncthreads();
    __half* hb = reinterpret_cast<__half*>(sm + 1024);
    zpack_store(hb, acc, wm, wn, g, c);
    __syncthreads();

    const int zb = m0 >> 11, mloc = m0 & 2047;
    uint4* dst = reinterpret_cast<uint4*>(Zp + (size_t)zb * NN * DD + (size_t)(mloc >> 5) * 4096);
    const uint4* src = reinterpret_cast<const uint4*>(hb);
    #pragma unroll 1
    for (int i2 = tid; i2 < 2048; i2 += 256)
        dst[i2] = src[i2];
}

// =================================================================
//  fused_rz: x = relu((p0+p1+bias)*invden) (never materialized),
//  then Z = x @ W (whole W in smem, barrier-free), packed-fp16 out.
//  NOTE: x tile holds FULL 128 features per row -> needs its own
//  row stride APAD_FZ=132 (134 KB smem total, occupancy 1).
// =================================================================
#define APAD_FZ 132
#define FX_TB (128 * APAD_FZ * 4)             // 67584
#define FW_OFF (1024 + FX_TB)                 // 68608
#define SMEM_FZ (FW_OFF + 128 * WPAD * 4)     // 68608 + 69632 = 138240

template<bool FIRST>
__global__ __launch_bounds__(256, 1) void fused_rz(
    const float* __restrict__ part,
    const float* __restrict__ rs,
    float* __restrict__ invd,
    const float* __restrict__ bias,
    const float* __restrict__ W,
    __half* __restrict__ Zp)
{
    extern __shared__ __align__(16) char sm[];
    const uint32_t smb = smem_u32(sm);
    const int tid = threadIdx.x, lane = tid & 31, wid = tid >> 5;
    const int m0 = blockIdx.x * 128;

    // async-load whole W (64 KB)
    {
        const int k = tid >> 1, nh = tid & 1;
        const float* wsrc = W + (size_t)k * DD + nh * 64;
        const uint32_t wdst = smb + FW_OFF + (uint32_t)(k * WPAD + nh * 64) * 4;
        #pragma unroll
        for (int j = 0; j < 16; j++) cp16(wdst + j * 16, wsrc + j * 4);
        cp_commit();
    }

    // x tile into As (overlapped with W load latency)
    float* As = reinterpret_cast<float*>(sm + 1024);
    {
        const int tr = tid >> 1, fh = (tid & 1) * 64;
        const size_t tok = (size_t)(m0 + tr);
        float inv;
        if (FIRST) {
            inv = 1.0f / (rs[tok] + rs[(size_t)BB * NN + tok] + 1.0f);
            if ((tid & 1) == 0) invd[tok] = inv;
        } else {
            inv = invd[tok];
        }
        const float4* p0 = reinterpret_cast<const float4*>(part + tok * DD + fh);
        const float4* p1 = reinterpret_cast<const float4*>(part + (size_t)BB * NN * DD + tok * DD + fh);
        #pragma unroll
        for (int j = 0; j < 16; j++) {
            float4 a = p0[j], b2 = p1[j];
            float4 bv = *reinterpret_cast<const float4*>(bias + fh + j * 4);
            float4 o;
            o.x = fmaxf((a.x + b2.x + bv.x) * inv, 0.f);
            o.y = fmaxf((a.y + b2.y + bv.y) * inv, 0.f);
            o.z = fmaxf((a.z + b2.z + bv.z) * inv, 0.f);
            o.w = fmaxf((a.w + b2.w + bv.w) * inv, 0.f);
            *reinterpret_cast<float4*>(As + tr * APAD_FZ + fh + j * 4) = o;
        }
    }
    asm volatile("cp.async.wait_group 0;" ::: "memory");
    __syncthreads();

    const int g = lane >> 2, c = lane & 3;
    const int wm = (wid & 3) * 32, wn = (wid >> 2) * 64;
    const uint32_t* Wu = reinterpret_cast<const uint32_t*>(sm + FW_OFF);

    float acc[2][8][4];
    #pragma unroll
    for (int mi = 0; mi < 2; mi++)
        #pragma unroll
        for (int nj = 0; nj < 8; nj++)
            #pragma unroll
            for (int q = 0; q < 4; q++) acc[mi][nj][q] = 0.f;

    #pragma unroll 1
    for (int ks8 = 0; ks8 < 16; ks8++) {
        const int kk = ks8 * 8 + c;
        uint32_t a0[4], a1[4];
        a0[0] = cvt_tf32(As[(wm + g)      * APAD_FZ + kk]);
        a0[1] = cvt_tf32(As[(wm + g + 8)  * APAD_FZ + kk]);
        a0[2] = cvt_tf32(As[(wm + g)      * APAD_FZ + kk + 4]);
        a0[3] = cvt_tf32(As[(wm + g + 8)  * APAD_FZ + kk + 4]);
        a1[0] = cvt_tf32(As[(wm + 16 + g) * APAD_FZ + kk]);
        a1[1] = cvt_tf32(As[(wm + 24 + g) * APAD_FZ + kk]);
        a1[2] = cvt_tf32(As[(wm + 16 + g) * APAD_FZ + kk + 4]);
        a1[3] = cvt_tf32(As[(wm + 24 + g) * APAD_FZ + kk + 4]);
        #pragma unroll
        for (int nj = 0; nj < 8; nj++) {
            const int col = wn + 8 * nj + g;
            uint32_t b0 = cvt_tf32(__uint_as_float(Wu[kk       * WPAD + col]));
            uint32_t b1 = cvt_tf32(__uint_as_float(Wu[(kk + 4) * WPAD + col]));
            mma_tf32(acc[0][nj], a0[0], a0[1], a0[2], a0[3], b0, b1);
            mma_tf32(acc[1][nj], a1[0], a1[1], a1[2], a1[3], b0, b1);
        }
    }

    __syncthreads();
    __half* hb = reinterpret_cast<__half*>(sm + 1024);
    zpack_store(hb, acc, wm, wn, g, c);
    __syncthreads();

    const int zb = m0 >> 11, mloc = m0 & 2047;
    uint4* dst = reinterpret_cast<uint4*>(Zp + (size_t)zb * NN * DD + (size_t)(mloc >> 5) * 4096);
    const uint4* src = reinterpret_cast<const uint4*>(hb);
    #pragma unroll 1
    for (int i2 = tid; i2 < 2048; i2 += 256)
        dst[i2] = src[i2];
}

// =================================================================
//  Final reduce: out = relu((p0 + p1 + bias) * invden)
// =================================================================
__global__ __launch_bounds__(256, 8) void reduce_fin(
    const float* __restrict__ part,
    const float* __restrict__ bias,
    const float* __restrict__ invd,
    float* __restrict__ out)
{
    const size_t base = ((size_t)blockIdx.x * 256 + threadIdx.x) * 4;
    const int f0 = (int)(base & 127);
    const size_t tg = base >> 7;
    const float inv = invd[tg];

    float4 p0 = *reinterpret_cast<const float4*>(part + base);
    float4 p1 = *reinterpret_cast<const float4*>(part + (size_t)BB * NN * DD + base);
    float4 bv = *reinterpret_cast<const float4*>(bias + f0);
    float4 o;
    o.x = fmaxf((p0.x + p1.x + bv.x) * inv, 0.f);
    o.y = fmaxf((p0.y + p1.y + bv.y) * inv, 0.f);
    o.z = fmaxf((p0.z + p1.z + bv.z) * inv, 0.f);
    o.w = fmaxf((p0.w + p1.w + bv.w) * inv, 0.f);
    *reinterpret_cast<float4*>(out + base) = o;
}

// =================================================================
extern "C" void kernel_launch(void* const* d_in, const int* in_sizes, int n_in,
                              void* d_out, int out_size)
{
    const float *inputs = nullptr, *adj = nullptr, *W = nullptr, *bias = nullptr;
    for (int i = 0; i < n_in; i++) {
        const long long s = in_sizes[i];
        if      (s == (long long)BB * NN * DD) inputs = (const float*)d_in[i];
        else if (s == (long long)BB * NN * NN) adj    = (const float*)d_in[i];
        else if (s == 3LL * DD * DD)           W      = (const float*)d_in[i];
        else if (s == 3LL * DD)                bias   = (const float*)d_in[i];
    }
    float* out = (float*)d_out;

    __half *a16, *zp;
    float *part, *rsv, *invd;
    cudaGetSymbolAddress((void**)&a16,  g_a16);
    cudaGetSymbolAddress((void**)&zp,   g_zpk);
    cudaGetSymbolAddress((void**)&part, g_part);
    cudaGetSymbolAddress((void**)&rsv,  g_rs);
    cudaGetSymbolAddress((void**)&invd, g_invden);

    static bool attr_done = false;
    if (!attr_done) {
        cudaFuncSetAttribute(ax_first,        cudaFuncAttributeMaxDynamicSharedMemorySize, SMEM_AX0);
        cudaFuncSetAttribute(ax_rest,         cudaFuncAttributeMaxDynamicSharedMemorySize, SMEM_AX12);
        cudaFuncSetAttribute(zk_t,            cudaFuncAttributeMaxDynamicSharedMemorySize, SMEM_ZK);
        cudaFuncSetAttribute(fused_rz<true>,  cudaFuncAttributeMaxDynamicSharedMemorySize, SMEM_FZ);
        cudaFuncSetAttribute(fused_rz<false>, cudaFuncAttributeMaxDynamicSharedMemorySize, SMEM_FZ);
        attr_done = true;
    }

    const dim3 gAX(NN / 128, BB, 2);          // 256 CTAs (split-K x2)
    const int  gZ = (BB * NN) / 128;          // 128 CTAs
    const int  gRED = (BB * NN * DD) / 1024;  // 2048 CTAs

    // layer 0
    zk_t<<<gZ, 256, SMEM_ZK>>>(inputs, W, zp);
    ax_first<<<gAX, 256, SMEM_AX0>>>(adj, zp, part, rsv, a16);
    // reduce0 + zk1
    fused_rz<true ><<<gZ, 256, SMEM_FZ>>>(part, rsv, invd, bias, W + DD * DD, zp);
    // layer 1
    ax_rest<<<gAX, 256, SMEM_AX12>>>(a16, zp, part);
    // reduce1 + zk2
    fused_rz<false><<<gZ, 256, SMEM_FZ>>>(part, nullptr, invd, bias + DD, W + 2 * DD * DD, zp);
    // layer 2
    ax_rest<<<gAX, 256, SMEM_AX12>>>(a16, zp, part);
    reduce_fin<<<gRED, 256>>>(part, bias + 2 * DD, invd, out);
}